// round 2
// baseline (speedup 1.0000x reference)
#include <cuda_runtime.h>

// Problem constants
#define B_SZ    16
#define L_LEN   2048
#define H_DIM   512
#define N_DIM   512
#define T_CH    16                 // chunk length
#define C_CH    (L_LEN / T_CH)     // 128 chunks
#define OUT_MAIN (B_SZ * L_LEN * N_DIM)
#define BPAD    20                 // padded batch-row stride (floats), 16B aligned

// ---------------- scratch (device globals; no allocations allowed) ----------
__device__ float g_bx[L_LEN * B_SZ * N_DIM];   // Bx projections  [t][b][n]  (64MB)
__device__ float g_f [C_CH * B_SZ * N_DIM];    // chunk local finals [c][b][n]
__device__ float g_H [C_CH * B_SZ * N_DIM];    // true chunk entry states [c][b][n]
__device__ float g_P1[N_DIM * N_DIM];
__device__ float g_P2[N_DIM * N_DIM];
__device__ unsigned int g_bar;                 // zero-initialized at load
__device__ unsigned int g_done;

// acc[bb] += a * hvec.{x,y,z,w}  (4 batches)
#define FMA4(arr, aval, hv) \
    arr[0] += (aval) * (hv).x; arr[1] += (aval) * (hv).y; \
    arr[2] += (aval) * (hv).z; arr[3] += (aval) * (hv).w;

// 64 FMAs: 4 rows (A0..A3 are float4 over k) x 4 k x 4 batches (H0..H3)
#define TILE_FMA() \
    FMA4(acc0, Av0.x, Hv0) FMA4(acc0, Av0.y, Hv1) FMA4(acc0, Av0.z, Hv2) FMA4(acc0, Av0.w, Hv3) \
    FMA4(acc1, Av1.x, Hv0) FMA4(acc1, Av1.y, Hv1) FMA4(acc1, Av1.z, Hv2) FMA4(acc1, Av1.w, Hv3) \
    FMA4(acc2, Av2.x, Hv0) FMA4(acc2, Av2.y, Hv1) FMA4(acc2, Av2.z, Hv2) FMA4(acc2, Av2.w, Hv3) \
    FMA4(acc3, Av3.x, Hv0) FMA4(acc3, Av3.y, Hv1) FMA4(acc3, Av3.z, Hv2) FMA4(acc3, Av3.w, Hv3)

// ---------------- Phase 1: bx[t][b][n] = sum_h Bm[n][h] * x[b][t][h] -------
// 512 threads = 128 row-groups (4 rows each) x 4 batch-groups (4 batches each)
__global__ __launch_bounds__(512) void proj_kernel(const float* __restrict__ x,
                                                   const float* __restrict__ Bm)
{
    __shared__ float xs[H_DIM * BPAD];         // [h][b], 40 KB
    const int t  = blockIdx.x;
    const int bg = threadIdx.x & 3;
    const int rg = threadIdx.x >> 2;

    // stage x[:, t, :] into smem (k-major, batch minor)
    {
        const int k = threadIdx.x;
        #pragma unroll
        for (int b = 0; b < B_SZ; b++)
            xs[k * BPAD + b] = x[((size_t)b * L_LEN + t) * H_DIM + k];
    }
    __syncthreads();

    float acc0[4] = {0,0,0,0}, acc1[4] = {0,0,0,0};
    float acc2[4] = {0,0,0,0}, acc3[4] = {0,0,0,0};

    const int n0 = rg * 4;
    const float4* w0 = reinterpret_cast<const float4*>(Bm + (size_t)(n0 + 0) * H_DIM);
    const float4* w1 = reinterpret_cast<const float4*>(Bm + (size_t)(n0 + 1) * H_DIM);
    const float4* w2 = reinterpret_cast<const float4*>(Bm + (size_t)(n0 + 2) * H_DIM);
    const float4* w3 = reinterpret_cast<const float4*>(Bm + (size_t)(n0 + 3) * H_DIM);
    const float* xp = xs + bg * 4;

    #pragma unroll 2
    for (int k4 = 0; k4 < H_DIM / 4; k4++) {
        const float4 Av0 = w0[k4], Av1 = w1[k4], Av2 = w2[k4], Av3 = w3[k4];
        const float4 Hv0 = *reinterpret_cast<const float4*>(xp + (4*k4 + 0) * BPAD);
        const float4 Hv1 = *reinterpret_cast<const float4*>(xp + (4*k4 + 1) * BPAD);
        const float4 Hv2 = *reinterpret_cast<const float4*>(xp + (4*k4 + 2) * BPAD);
        const float4 Hv3 = *reinterpret_cast<const float4*>(xp + (4*k4 + 3) * BPAD);
        TILE_FMA();
    }

    #pragma unroll
    for (int bb = 0; bb < 4; bb++) {
        float4 v; v.x = acc0[bb]; v.y = acc1[bb]; v.z = acc2[bb]; v.w = acc3[bb];
        *reinterpret_cast<float4*>(
            g_bx + ((size_t)t * B_SZ + (bg*4 + bb)) * N_DIM + n0) = v;
    }
}

// ---------------- SGEMM for repeated squaring: Y = X @ X (512x512) ---------
// SRC/DST: 0 = external A, 1 = g_P1, 2 = g_P2 (no host symbol lookups needed)
template <int SRC, int DST>
__global__ void matsq_kernel(const float* __restrict__ Aext)
{
    const float* X = (SRC == 0) ? Aext : (SRC == 1 ? g_P1 : g_P2);
    float*       Y = (DST == 1) ? g_P1 : g_P2;

    __shared__ float As[16][16];
    __shared__ float Bs[16][17];
    const int tx = threadIdx.x, ty = threadIdx.y;
    const int row = blockIdx.y * 16 + ty;
    const int col = blockIdx.x * 16 + tx;
    float acc = 0.0f;
    for (int kt = 0; kt < N_DIM / 16; kt++) {
        As[ty][tx] = X[row * N_DIM + kt * 16 + tx];
        Bs[ty][tx] = X[(kt * 16 + ty) * N_DIM + col];
        __syncthreads();
        #pragma unroll
        for (int kk = 0; kk < 16; kk++) acc += As[ty][kk] * Bs[kk][tx];
        __syncthreads();
    }
    Y[row * N_DIM + col] = acc;
}

// ---------------- boundary scan: S_{c+1} = A^16 S_c + f_c ------------------
// 128 CTAs x 256 threads, all resident. Spin barrier on gmem.
__device__ __forceinline__ void grid_barrier(unsigned int target)
{
    __syncthreads();
    __threadfence();
    if (threadIdx.x == 0) {
        atomicAdd(&g_bar, 1u);
        while (*(volatile unsigned int*)&g_bar < target) { __nanosleep(64); }
    }
    __threadfence();
    __syncthreads();
}

__global__ __launch_bounds__(256) void boundary_kernel()
{
    const int tid = threadIdx.x;
    const int seg = tid & 3;          // k-segment (4-way split of k)
    const int ol  = tid >> 2;         // 0..63: output within CTA
    const int r   = ol >> 4;          // 0..3
    const int b   = ol & 15;          // 0..15
    const int n   = blockIdx.x * 4 + r;
    const unsigned int G = gridDim.x;

    // zero S_0 (first 16*512 floats of g_H), one writer per element
    if (seg == 0) g_H[blockIdx.x * 64 + ol] = 0.0f;
    unsigned int phase = 1;
    grid_barrier(phase * G);

    const float4* ap = reinterpret_cast<const float4*>(g_P2 + (size_t)n * N_DIM) + seg * 32;
    for (int c = 0; c < C_CH - 1; c++) {
        const float4* sc = reinterpret_cast<const float4*>(
            g_H + ((size_t)c * B_SZ + b) * N_DIM) + seg * 32;
        float acc = 0.0f;
        #pragma unroll 8
        for (int k4 = 0; k4 < 32; k4++) {
            const float4 a = ap[k4], s = sc[k4];
            acc += a.x * s.x + a.y * s.y + a.z * s.z + a.w * s.w;
        }
        acc += __shfl_xor_sync(0xffffffffu, acc, 1);
        acc += __shfl_xor_sync(0xffffffffu, acc, 2);
        if (seg == 0)
            g_H[(((size_t)(c + 1)) * B_SZ + b) * N_DIM + n] =
                acc + g_f[((size_t)c * B_SZ + b) * N_DIM + n];
        phase++;
        grid_barrier(phase * G);
    }

    // reset barrier state for the next graph replay (everyone has passed the
    // final barrier before the last CTA performs the reset)
    if (tid == 0) {
        unsigned int d = atomicAdd(&g_done, 1u);
        if (d == G - 1) {
            g_bar = 0;
            __threadfence();
            g_done = 0;
            __threadfence();
        }
    }
}

// ---------------- Chunk scan kernels (one CTA per chunk) -------------------
// smem h: [k(512)][b(16) padded to 20] = 40 KB, single buffer + 2 syncs/step
template <bool FIRST_PASS>
__global__ __launch_bounds__(512) void scan_kernel(const float* __restrict__ A,
                                                   float* __restrict__ out,
                                                   int out_size)
{
    __shared__ float hs[N_DIM * BPAD];         // 40 KB
    const int c  = blockIdx.x;
    const int bg = threadIdx.x & 3;
    const int rg = threadIdx.x >> 2;
    const int n0 = rg * 4;

    // init h_in
    if (FIRST_PASS) {
        #pragma unroll
        for (int rr = 0; rr < 4; rr++)
            #pragma unroll
            for (int bb = 0; bb < 4; bb++)
                hs[(n0 + rr) * BPAD + bg*4 + bb] = 0.0f;
    } else {
        #pragma unroll
        for (int bb = 0; bb < 4; bb++) {
            const float4 v = *reinterpret_cast<const float4*>(
                g_H + ((size_t)c * B_SZ + (bg*4 + bb)) * N_DIM + n0);
            hs[(n0 + 0) * BPAD + bg*4 + bb] = v.x;
            hs[(n0 + 1) * BPAD + bg*4 + bb] = v.y;
            hs[(n0 + 2) * BPAD + bg*4 + bb] = v.z;
            hs[(n0 + 3) * BPAD + bg*4 + bb] = v.w;
        }
    }
    __syncthreads();

    const float4* a0 = reinterpret_cast<const float4*>(A + (size_t)(n0 + 0) * N_DIM);
    const float4* a1 = reinterpret_cast<const float4*>(A + (size_t)(n0 + 1) * N_DIM);
    const float4* a2 = reinterpret_cast<const float4*>(A + (size_t)(n0 + 2) * N_DIM);
    const float4* a3 = reinterpret_cast<const float4*>(A + (size_t)(n0 + 3) * N_DIM);
    const float* hp = hs + bg * 4;

    float acc0[4], acc1[4], acc2[4], acc3[4];

    for (int j = 0; j < T_CH; j++) {
        const int t = c * T_CH + j;

        // acc = bx[t][b][n0..n0+3]
        #pragma unroll
        for (int bb = 0; bb < 4; bb++) {
            const float4 v = *reinterpret_cast<const float4*>(
                g_bx + ((size_t)t * B_SZ + (bg*4 + bb)) * N_DIM + n0);
            acc0[bb] = v.x; acc1[bb] = v.y; acc2[bb] = v.z; acc3[bb] = v.w;
        }

        #pragma unroll 2
        for (int k4 = 0; k4 < N_DIM / 4; k4++) {
            const float4 Av0 = a0[k4], Av1 = a1[k4], Av2 = a2[k4], Av3 = a3[k4];
            const float4 Hv0 = *reinterpret_cast<const float4*>(hp + (4*k4 + 0) * BPAD);
            const float4 Hv1 = *reinterpret_cast<const float4*>(hp + (4*k4 + 1) * BPAD);
            const float4 Hv2 = *reinterpret_cast<const float4*>(hp + (4*k4 + 2) * BPAD);
            const float4 Hv3 = *reinterpret_cast<const float4*>(hp + (4*k4 + 3) * BPAD);
            TILE_FMA();
        }

        __syncthreads();   // all reads of old h done

        // publish h_new (row-major n, batch minor), float4 over batches
        #pragma unroll
        for (int rr = 0; rr < 4; rr++) {
            float4 v;
            const float* ar = (rr == 0) ? acc0 : (rr == 1) ? acc1 : (rr == 2) ? acc2 : acc3;
            v.x = ar[0]; v.y = ar[1]; v.z = ar[2]; v.w = ar[3];
            *reinterpret_cast<float4*>(hs + (n0 + rr) * BPAD + bg*4) = v;
        }

        if (!FIRST_PASS) {
            #pragma unroll
            for (int bb = 0; bb < 4; bb++) {
                float4 v; v.x = acc0[bb]; v.y = acc1[bb]; v.z = acc2[bb]; v.w = acc3[bb];
                *reinterpret_cast<float4*>(
                    out + ((size_t)(bg*4 + bb) * L_LEN + t) * N_DIM + n0) = v;
            }
        }
        __syncthreads();   // h_new visible
    }

    if (FIRST_PASS) {
        // chunk-final state from last acc
        #pragma unroll
        for (int bb = 0; bb < 4; bb++) {
            float4 v; v.x = acc0[bb]; v.y = acc1[bb]; v.z = acc2[bb]; v.w = acc3[bb];
            *reinterpret_cast<float4*>(
                g_f + ((size_t)c * B_SZ + (bg*4 + bb)) * N_DIM + n0) = v;
        }
    } else if (c == C_CH - 1 && out_size >= OUT_MAIN + N_DIM * B_SZ) {
        // h_final in (N, B) layout appended after main output
        #pragma unroll
        for (int rr = 0; rr < 4; rr++) {
            const float* ar = (rr == 0) ? acc0 : (rr == 1) ? acc1 : (rr == 2) ? acc2 : acc3;
            #pragma unroll
            for (int bb = 0; bb < 4; bb++)
                out[OUT_MAIN + (size_t)(n0 + rr) * B_SZ + (bg*4 + bb)] = ar[bb];
        }
    }
}

// ---------------- launch ----------------------------------------------------
extern "C" void kernel_launch(void* const* d_in, const int* in_sizes, int n_in,
                              void* d_out, int out_size)
{
    const float* x  = (const float*)d_in[0];   // (B, L, H)
    const float* A  = (const float*)d_in[1];   // (N, N)
    const float* Bm = (const float*)d_in[2];   // (N, H)
    float* out = (float*)d_out;

    // A^16 by repeated squaring (independent of proj/pass1; tiny)
    dim3 sgrid(N_DIM / 16, N_DIM / 16), sblk(16, 16);
    matsq_kernel<0, 1><<<sgrid, sblk>>>(A);        // P1 = A^2
    matsq_kernel<1, 2><<<sgrid, sblk>>>(nullptr);  // P2 = A^4
    matsq_kernel<2, 1><<<sgrid, sblk>>>(nullptr);  // P1 = A^8
    matsq_kernel<1, 2><<<sgrid, sblk>>>(nullptr);  // P2 = A^16

    // 1) input projection -> g_bx[t][b][n]
    proj_kernel<<<L_LEN, 512>>>(x, Bm);

    // 2) local chunk scans (zero init) -> chunk finals g_f
    scan_kernel<true><<<C_CH, 512>>>(A, nullptr, 0);

    // 3) boundary scan: S_{c+1} = A^16 S_c + f_c  (127 sequential steps)
    boundary_kernel<<<C_CH, 256>>>();

    // 4) true chunk scans from S_c, writing outputs (+ h_final)
    scan_kernel<false><<<C_CH, 512>>>(A, out, out_size);
}

// round 3
// speedup vs baseline: 1.1838x; 1.1838x over previous
#include <cuda_runtime.h>

// Problem constants
#define B_SZ    16
#define L_LEN   2048
#define H_DIM   512
#define N_DIM   512
#define T_CH    16                 // chunk length
#define C_CH    (L_LEN / T_CH)     // 128 chunks
#define OUT_MAIN (B_SZ * L_LEN * N_DIM)
#define BPAD    20                 // padded batch-row stride (floats), 16B aligned

// ---------------- scratch (device globals; no allocations allowed) ----------
__device__ float g_bx[L_LEN * B_SZ * N_DIM];   // Bx projections  [t][b][n]  (64MB)
__device__ float g_f [C_CH * B_SZ * N_DIM];    // chunk local finals [c][b][n]
__device__ float g_XA[C_CH * B_SZ * N_DIM];    // Kogge-Stone ping
__device__ float g_XB[C_CH * B_SZ * N_DIM];    // Kogge-Stone pong
__device__ float g_P1[N_DIM * N_DIM];
__device__ float g_P2[N_DIM * N_DIM];
__device__ float g_Mp[7 * N_DIM * N_DIM];      // M^(2^d), M = A^16, d=0..6

// acc[bb] += a * hvec.{x,y,z,w}  (4 batches)
#define FMA4(arr, aval, hv) \
    arr[0] += (aval) * (hv).x; arr[1] += (aval) * (hv).y; \
    arr[2] += (aval) * (hv).z; arr[3] += (aval) * (hv).w;

// 64 FMAs: 4 rows (Av0..Av3 are float4 over k) x 4 k x 4 batches (Hv0..Hv3)
#define TILE_FMA() \
    FMA4(acc0, Av0.x, Hv0) FMA4(acc0, Av0.y, Hv1) FMA4(acc0, Av0.z, Hv2) FMA4(acc0, Av0.w, Hv3) \
    FMA4(acc1, Av1.x, Hv0) FMA4(acc1, Av1.y, Hv1) FMA4(acc1, Av1.z, Hv2) FMA4(acc1, Av1.w, Hv3) \
    FMA4(acc2, Av2.x, Hv0) FMA4(acc2, Av2.y, Hv1) FMA4(acc2, Av2.z, Hv2) FMA4(acc2, Av2.w, Hv3) \
    FMA4(acc3, Av3.x, Hv0) FMA4(acc3, Av3.y, Hv1) FMA4(acc3, Av3.z, Hv2) FMA4(acc3, Av3.w, Hv3)

// ---------------- Phase 1: bx[t][b][n] = sum_h Bm[n][h] * x[b][t][h] -------
__global__ __launch_bounds__(512) void proj_kernel(const float* __restrict__ x,
                                                   const float* __restrict__ Bm)
{
    __shared__ float xs[H_DIM * BPAD];         // [h][b], 40 KB
    const int t  = blockIdx.x;
    const int bg = threadIdx.x & 3;
    const int rg = threadIdx.x >> 2;

    {
        const int k = threadIdx.x;
        #pragma unroll
        for (int b = 0; b < B_SZ; b++)
            xs[k * BPAD + b] = x[((size_t)b * L_LEN + t) * H_DIM + k];
    }
    __syncthreads();

    float acc0[4] = {0,0,0,0}, acc1[4] = {0,0,0,0};
    float acc2[4] = {0,0,0,0}, acc3[4] = {0,0,0,0};

    const int n0 = rg * 4;
    const float4* w0 = reinterpret_cast<const float4*>(Bm + (size_t)(n0 + 0) * H_DIM);
    const float4* w1 = reinterpret_cast<const float4*>(Bm + (size_t)(n0 + 1) * H_DIM);
    const float4* w2 = reinterpret_cast<const float4*>(Bm + (size_t)(n0 + 2) * H_DIM);
    const float4* w3 = reinterpret_cast<const float4*>(Bm + (size_t)(n0 + 3) * H_DIM);
    const float* xp = xs + bg * 4;

    #pragma unroll 2
    for (int k4 = 0; k4 < H_DIM / 4; k4++) {
        const float4 Av0 = w0[k4], Av1 = w1[k4], Av2 = w2[k4], Av3 = w3[k4];
        const float4 Hv0 = *reinterpret_cast<const float4*>(xp + (4*k4 + 0) * BPAD);
        const float4 Hv1 = *reinterpret_cast<const float4*>(xp + (4*k4 + 1) * BPAD);
        const float4 Hv2 = *reinterpret_cast<const float4*>(xp + (4*k4 + 2) * BPAD);
        const float4 Hv3 = *reinterpret_cast<const float4*>(xp + (4*k4 + 3) * BPAD);
        TILE_FMA();
    }

    #pragma unroll
    for (int bb = 0; bb < 4; bb++) {
        float4 v; v.x = acc0[bb]; v.y = acc1[bb]; v.z = acc2[bb]; v.w = acc3[bb];
        *reinterpret_cast<float4*>(
            g_bx + ((size_t)t * B_SZ + (bg*4 + bb)) * N_DIM + n0) = v;
    }
}

// ---------------- SGEMM: Y = X @ X (512x512), 64x64 tiles ------------------
// sel: 0=external A, 1=g_P1, 2=g_P2, 10+d = g_Mp[d]
__device__ __forceinline__ const float* mat_sel(const float* Aext, int s)
{
    if (s == 0) return Aext;
    if (s == 1) return g_P1;
    if (s == 2) return g_P2;
    return g_Mp + (size_t)(s - 10) * N_DIM * N_DIM;
}
__device__ __forceinline__ float* mat_sel_w(int s)
{
    if (s == 1) return g_P1;
    if (s == 2) return g_P2;
    return g_Mp + (size_t)(s - 10) * N_DIM * N_DIM;
}

__global__ __launch_bounds__(256) void matsq_kernel(const float* __restrict__ Aext,
                                                    int src_sel, int dst_sel)
{
    const float* __restrict__ X = mat_sel(Aext, src_sel);
    float* __restrict__ Y = mat_sel_w(dst_sel);

    __shared__ float As[16][68];   // [k][i]
    __shared__ float Bs[16][68];   // [k][j]
    const int tid = threadIdx.x;
    const int tx = tid & 15, ty = tid >> 4;
    const int i0 = blockIdx.y * 64, j0 = blockIdx.x * 64;

    float acc[4][4] = {};

    for (int kt = 0; kt < N_DIM; kt += 16) {
        // A tile: X[i0+i][kt+k] -> As[k][i]; 1024 elems, 4/thread (float4 over k)
        {
            const int e = tid * 4;
            const int i = e >> 4, k = e & 15;
            const float4 v = *reinterpret_cast<const float4*>(X + (size_t)(i0 + i) * N_DIM + kt + k);
            As[k + 0][i] = v.x; As[k + 1][i] = v.y; As[k + 2][i] = v.z; As[k + 3][i] = v.w;
        }
        // B tile: X[kt+k][j0+j] -> Bs[k][j]; float4 over j
        {
            const int e = tid * 4;
            const int k = e >> 6, j = e & 63;
            const float4 v = *reinterpret_cast<const float4*>(X + (size_t)(kt + k) * N_DIM + j0 + j);
            *reinterpret_cast<float4*>(&Bs[k][j]) = v;
        }
        __syncthreads();

        #pragma unroll
        for (int kk = 0; kk < 16; kk++) {
            const float4 a = *reinterpret_cast<const float4*>(&As[kk][ty * 4]);
            const float4 b = *reinterpret_cast<const float4*>(&Bs[kk][tx * 4]);
            acc[0][0] += a.x * b.x; acc[0][1] += a.x * b.y; acc[0][2] += a.x * b.z; acc[0][3] += a.x * b.w;
            acc[1][0] += a.y * b.x; acc[1][1] += a.y * b.y; acc[1][2] += a.y * b.z; acc[1][3] += a.y * b.w;
            acc[2][0] += a.z * b.x; acc[2][1] += a.z * b.y; acc[2][2] += a.z * b.z; acc[2][3] += a.z * b.w;
            acc[3][0] += a.w * b.x; acc[3][1] += a.w * b.y; acc[3][2] += a.w * b.z; acc[3][3] += a.w * b.w;
        }
        __syncthreads();
    }

    #pragma unroll
    for (int r = 0; r < 4; r++) {
        float4 v; v.x = acc[r][0]; v.y = acc[r][1]; v.z = acc[r][2]; v.w = acc[r][3];
        *reinterpret_cast<float4*>(Y + (size_t)(i0 + ty * 4 + r) * N_DIM + j0 + tx * 4) = v;
    }
}

// ---------------- Kogge-Stone level: x'_c = M^(2^d) x_{c-2^d} + x_c --------
// sel: 0 = g_f, 1 = g_XA, 2 = g_XB
__device__ __forceinline__ const float* ks_sel(int s)
{
    if (s == 0) return g_f;
    return (s == 1) ? g_XA : g_XB;
}
__device__ __forceinline__ float* ks_sel_w(int s)
{
    return (s == 1) ? g_XA : g_XB;
}

__global__ __launch_bounds__(512) void ks_level_kernel(int d, int src_sel, int dst_sel)
{
    const float* __restrict__ src = ks_sel(src_sel);
    float* __restrict__ dst = ks_sel_w(dst_sel);
    const int c = blockIdx.x;
    const int shift = 1 << d;

    if (c < shift) {
        // pass-through copy
        const int n = threadIdx.x;
        #pragma unroll
        for (int b = 0; b < B_SZ; b++)
            dst[((size_t)c * B_SZ + b) * N_DIM + n] = src[((size_t)c * B_SZ + b) * N_DIM + n];
        return;
    }

    __shared__ float xs[N_DIM * BPAD];         // x_{c-shift} as [k][b], 40 KB
    const float* __restrict__ M = g_Mp + (size_t)d * N_DIM * N_DIM;
    const int bg = threadIdx.x & 3;
    const int rg = threadIdx.x >> 2;
    const int n0 = rg * 4;

    {
        const int k = threadIdx.x;
        const float* sp = src + (size_t)(c - shift) * B_SZ * N_DIM;
        #pragma unroll
        for (int b = 0; b < B_SZ; b++)
            xs[k * BPAD + b] = sp[(size_t)b * N_DIM + k];
    }
    __syncthreads();

    float acc0[4], acc1[4], acc2[4], acc3[4];
    #pragma unroll
    for (int bb = 0; bb < 4; bb++) {
        const float4 v = *reinterpret_cast<const float4*>(
            src + ((size_t)c * B_SZ + (bg*4 + bb)) * N_DIM + n0);
        acc0[bb] = v.x; acc1[bb] = v.y; acc2[bb] = v.z; acc3[bb] = v.w;
    }

    const float4* m0 = reinterpret_cast<const float4*>(M + (size_t)(n0 + 0) * N_DIM);
    const float4* m1 = reinterpret_cast<const float4*>(M + (size_t)(n0 + 1) * N_DIM);
    const float4* m2 = reinterpret_cast<const float4*>(M + (size_t)(n0 + 2) * N_DIM);
    const float4* m3 = reinterpret_cast<const float4*>(M + (size_t)(n0 + 3) * N_DIM);
    const float* xp = xs + bg * 4;

    #pragma unroll 2
    for (int k4 = 0; k4 < N_DIM / 4; k4++) {
        const float4 Av0 = m0[k4], Av1 = m1[k4], Av2 = m2[k4], Av3 = m3[k4];
        const float4 Hv0 = *reinterpret_cast<const float4*>(xp + (4*k4 + 0) * BPAD);
        const float4 Hv1 = *reinterpret_cast<const float4*>(xp + (4*k4 + 1) * BPAD);
        const float4 Hv2 = *reinterpret_cast<const float4*>(xp + (4*k4 + 2) * BPAD);
        const float4 Hv3 = *reinterpret_cast<const float4*>(xp + (4*k4 + 3) * BPAD);
        TILE_FMA();
    }

    #pragma unroll
    for (int bb = 0; bb < 4; bb++) {
        float4 v; v.x = acc0[bb]; v.y = acc1[bb]; v.z = acc2[bb]; v.w = acc3[bb];
        *reinterpret_cast<float4*>(
            dst + ((size_t)c * B_SZ + (bg*4 + bb)) * N_DIM + n0) = v;
    }
}

// ---------------- Chunk scan kernels (one CTA per chunk) -------------------
// smem h: [k(512)][b(16) padded to 20] = 40 KB, single buffer + 2 syncs/step
template <bool FIRST_PASS>
__global__ __launch_bounds__(512) void scan_kernel(const float* __restrict__ A,
                                                   float* __restrict__ out,
                                                   int out_size)
{
    __shared__ float hs[N_DIM * BPAD];         // 40 KB
    const int c  = blockIdx.x;
    const int bg = threadIdx.x & 3;
    const int rg = threadIdx.x >> 2;
    const int n0 = rg * 4;

    // init h_in
    if (FIRST_PASS) {
        #pragma unroll
        for (int rr = 0; rr < 4; rr++)
            #pragma unroll
            for (int bb = 0; bb < 4; bb++)
                hs[(n0 + rr) * BPAD + bg*4 + bb] = 0.0f;
    } else {
        if (c == 0) {
            #pragma unroll
            for (int rr = 0; rr < 4; rr++)
                #pragma unroll
                for (int bb = 0; bb < 4; bb++)
                    hs[(n0 + rr) * BPAD + bg*4 + bb] = 0.0f;
        } else {
            // entry state = KS result of chunk c-1 (inclusive scan)
            #pragma unroll
            for (int bb = 0; bb < 4; bb++) {
                const float4 v = *reinterpret_cast<const float4*>(
                    g_XA + ((size_t)(c - 1) * B_SZ + (bg*4 + bb)) * N_DIM + n0);
                hs[(n0 + 0) * BPAD + bg*4 + bb] = v.x;
                hs[(n0 + 1) * BPAD + bg*4 + bb] = v.y;
                hs[(n0 + 2) * BPAD + bg*4 + bb] = v.z;
                hs[(n0 + 3) * BPAD + bg*4 + bb] = v.w;
            }
        }
    }
    __syncthreads();

    const float4* a0 = reinterpret_cast<const float4*>(A + (size_t)(n0 + 0) * N_DIM);
    const float4* a1 = reinterpret_cast<const float4*>(A + (size_t)(n0 + 1) * N_DIM);
    const float4* a2 = reinterpret_cast<const float4*>(A + (size_t)(n0 + 2) * N_DIM);
    const float4* a3 = reinterpret_cast<const float4*>(A + (size_t)(n0 + 3) * N_DIM);
    const float* hp = hs + bg * 4;

    float acc0[4], acc1[4], acc2[4], acc3[4];

    for (int j = 0; j < T_CH; j++) {
        const int t = c * T_CH + j;

        #pragma unroll
        for (int bb = 0; bb < 4; bb++) {
            const float4 v = *reinterpret_cast<const float4*>(
                g_bx + ((size_t)t * B_SZ + (bg*4 + bb)) * N_DIM + n0);
            acc0[bb] = v.x; acc1[bb] = v.y; acc2[bb] = v.z; acc3[bb] = v.w;
        }

        #pragma unroll 2
        for (int k4 = 0; k4 < N_DIM / 4; k4++) {
            const float4 Av0 = a0[k4], Av1 = a1[k4], Av2 = a2[k4], Av3 = a3[k4];
            const float4 Hv0 = *reinterpret_cast<const float4*>(hp + (4*k4 + 0) * BPAD);
            const float4 Hv1 = *reinterpret_cast<const float4*>(hp + (4*k4 + 1) * BPAD);
            const float4 Hv2 = *reinterpret_cast<const float4*>(hp + (4*k4 + 2) * BPAD);
            const float4 Hv3 = *reinterpret_cast<const float4*>(hp + (4*k4 + 3) * BPAD);
            TILE_FMA();
        }

        __syncthreads();   // all reads of old h done

        #pragma unroll
        for (int rr = 0; rr < 4; rr++) {
            float4 v;
            const float* ar = (rr == 0) ? acc0 : (rr == 1) ? acc1 : (rr == 2) ? acc2 : acc3;
            v.x = ar[0]; v.y = ar[1]; v.z = ar[2]; v.w = ar[3];
            *reinterpret_cast<float4*>(hs + (n0 + rr) * BPAD + bg*4) = v;
        }

        if (!FIRST_PASS) {
            #pragma unroll
            for (int bb = 0; bb < 4; bb++) {
                float4 v; v.x = acc0[bb]; v.y = acc1[bb]; v.z = acc2[bb]; v.w = acc3[bb];
                *reinterpret_cast<float4*>(
                    out + ((size_t)(bg*4 + bb) * L_LEN + t) * N_DIM + n0) = v;
            }
        }
        __syncthreads();   // h_new visible
    }

    if (FIRST_PASS) {
        #pragma unroll
        for (int bb = 0; bb < 4; bb++) {
            float4 v; v.x = acc0[bb]; v.y = acc1[bb]; v.z = acc2[bb]; v.w = acc3[bb];
            *reinterpret_cast<float4*>(
                g_f + ((size_t)c * B_SZ + (bg*4 + bb)) * N_DIM + n0) = v;
        }
    } else if (c == C_CH - 1 && out_size >= OUT_MAIN + N_DIM * B_SZ) {
        #pragma unroll
        for (int rr = 0; rr < 4; rr++) {
            const float* ar = (rr == 0) ? acc0 : (rr == 1) ? acc1 : (rr == 2) ? acc2 : acc3;
            #pragma unroll
            for (int bb = 0; bb < 4; bb++)
                out[OUT_MAIN + (size_t)(n0 + rr) * B_SZ + (bg*4 + bb)] = ar[bb];
        }
    }
}

// ---------------- launch ----------------------------------------------------
extern "C" void kernel_launch(void* const* d_in, const int* in_sizes, int n_in,
                              void* d_out, int out_size)
{
    const float* x  = (const float*)d_in[0];   // (B, L, H)
    const float* A  = (const float*)d_in[1];   // (N, N)
    const float* Bm = (const float*)d_in[2];   // (N, H)
    float* out = (float*)d_out;

    dim3 sgrid(N_DIM / 64, N_DIM / 64);        // 8x8 = 64 CTAs

    // 1) input projection -> g_bx[t][b][n]
    proj_kernel<<<L_LEN, 512>>>(x, Bm);

    // 2) local chunk scans (zero init) -> chunk finals g_f
    scan_kernel<true><<<C_CH, 512>>>(A, nullptr, 0);

    // 3) matrix powers: A^16 then M^(2^d) for d=0..6
    matsq_kernel<<<sgrid, 256>>>(A, 0, 1);       // P1 = A^2
    matsq_kernel<<<sgrid, 256>>>(A, 1, 2);       // P2 = A^4
    matsq_kernel<<<sgrid, 256>>>(A, 2, 1);       // P1 = A^8
    matsq_kernel<<<sgrid, 256>>>(A, 1, 10);      // Mp[0] = A^16
    matsq_kernel<<<sgrid, 256>>>(A, 10, 11);     // Mp[1] = A^32
    matsq_kernel<<<sgrid, 256>>>(A, 11, 12);     // Mp[2] = A^64
    matsq_kernel<<<sgrid, 256>>>(A, 12, 13);     // Mp[3] = A^128
    matsq_kernel<<<sgrid, 256>>>(A, 13, 14);     // Mp[4] = A^256
    matsq_kernel<<<sgrid, 256>>>(A, 14, 15);     // Mp[5] = A^512
    matsq_kernel<<<sgrid, 256>>>(A, 15, 16);     // Mp[6] = A^1024

    // 4) Kogge-Stone scan over chunk finals (7 levels, graph-edge sync)
    ks_level_kernel<<<C_CH, 512>>>(0, 0, 1);     // f  -> XA
    ks_level_kernel<<<C_CH, 512>>>(1, 1, 2);     // XA -> XB
    ks_level_kernel<<<C_CH, 512>>>(2, 2, 1);     // XB -> XA
    ks_level_kernel<<<C_CH, 512>>>(3, 1, 2);     // XA -> XB
    ks_level_kernel<<<C_CH, 512>>>(4, 2, 1);     // XB -> XA
    ks_level_kernel<<<C_CH, 512>>>(5, 1, 2);     // XA -> XB
    ks_level_kernel<<<C_CH, 512>>>(6, 2, 1);     // XB -> XA  (final in XA)

    // 5) true chunk scans from XA[c-1], writing outputs (+ h_final)
    scan_kernel<false><<<C_CH, 512>>>(A, out, out_size);
}

// round 4
// speedup vs baseline: 1.2098x; 1.0220x over previous
#include <cuda_runtime.h>

// Problem constants
#define B_SZ    16
#define L_LEN   2048
#define H_DIM   512
#define N_DIM   512
#define T_CH    16                 // chunk length
#define C_CH    (L_LEN / T_CH)     // 128 chunks
#define OUT_MAIN (B_SZ * L_LEN * N_DIM)
#define BPAD    20                 // padded batch-row stride (floats); 80B = 5*16B

// ---------------- scratch (device globals; no allocations allowed) ----------
__device__ float g_bx[L_LEN * B_SZ * N_DIM];   // Bx projections  [t][b][n]  (64MB)
__device__ float g_f [C_CH * B_SZ * N_DIM];    // chunk local finals [c][b][n]
__device__ float g_XA[C_CH * B_SZ * N_DIM];    // Kogge-Stone ping
__device__ float g_XB[C_CH * B_SZ * N_DIM];    // Kogge-Stone pong
__device__ float g_P1[N_DIM * N_DIM];
__device__ float g_P2[N_DIM * N_DIM];
__device__ float g_Mp[7 * N_DIM * N_DIM];      // M^(2^d), M = A^16, d=0..6

// ---------------- packed fp32x2 primitives (Blackwell) ----------------------
typedef unsigned long long u64;

#define FFMA2(acc, apk, hpk) \
    asm("fma.rn.f32x2 %0, %1, %2, %0;" : "+l"(acc) : "l"(apk), "l"(hpk))
#define PACK2(dst, f) \
    asm("mov.b64 %0, {%1, %1};" : "=l"(dst) : "f"(f))
#define PACKLOHI(dst, lo, hi) \
    asm("mov.b64 %0, {%1, %2};" : "=l"(dst) : "f"(lo), "f"(hi))
#define UNPK(lo, hi, src) \
    asm("mov.b64 {%0, %1}, %2;" : "=f"(lo), "=f"(hi) : "l"(src))

// One k-slice: 4 rows x 4 batches (2 packed pairs), hvp from [k][b] buffer
#define ONEK(base, off, c0, c1, c2, c3) do {                                   \
    const ulonglong2 hvp = *reinterpret_cast<const ulonglong2*>((base) + (off) * BPAD); \
    u64 ap;                                                                    \
    PACK2(ap, c0); FFMA2(acc0p[0], ap, hvp.x); FFMA2(acc0p[1], ap, hvp.y);     \
    PACK2(ap, c1); FFMA2(acc1p[0], ap, hvp.x); FFMA2(acc1p[1], ap, hvp.y);     \
    PACK2(ap, c2); FFMA2(acc2p[0], ap, hvp.x); FFMA2(acc2p[1], ap, hvp.y);     \
    PACK2(ap, c3); FFMA2(acc3p[0], ap, hvp.x); FFMA2(acc3p[1], ap, hvp.y);     \
} while (0)

// Full k-quad given 4 row-float4s over k
#define QUAD_FMA(base, k4) do {                                                \
    ONEK(base, 4*(k4) + 0, Av0.x, Av1.x, Av2.x, Av3.x);                        \
    ONEK(base, 4*(k4) + 1, Av0.y, Av1.y, Av2.y, Av3.y);                        \
    ONEK(base, 4*(k4) + 2, Av0.z, Av1.z, Av2.z, Av3.z);                        \
    ONEK(base, 4*(k4) + 3, Av0.w, Av1.w, Av2.w, Av3.w);                        \
} while (0)

// ---------------- Phase 1: bx[t][b][n] = sum_h Bm[n][h] * x[b][t][h] -------
__global__ __launch_bounds__(512) void proj_kernel(const float* __restrict__ x,
                                                   const float* __restrict__ Bm)
{
    __shared__ float xs[H_DIM * BPAD];         // [h][b], 40 KB
    const int t  = blockIdx.x;
    const int bg = threadIdx.x & 3;
    const int rg = threadIdx.x >> 2;

    {
        const int k = threadIdx.x;
        #pragma unroll
        for (int b = 0; b < B_SZ; b++)
            xs[k * BPAD + b] = x[((size_t)b * L_LEN + t) * H_DIM + k];
    }
    __syncthreads();

    u64 acc0p[2] = {0,0}, acc1p[2] = {0,0}, acc2p[2] = {0,0}, acc3p[2] = {0,0};

    const int n0 = rg * 4;
    const float4* w0 = reinterpret_cast<const float4*>(Bm + (size_t)(n0 + 0) * H_DIM);
    const float4* w1 = reinterpret_cast<const float4*>(Bm + (size_t)(n0 + 1) * H_DIM);
    const float4* w2 = reinterpret_cast<const float4*>(Bm + (size_t)(n0 + 2) * H_DIM);
    const float4* w3 = reinterpret_cast<const float4*>(Bm + (size_t)(n0 + 3) * H_DIM);
    const float* xp = xs + bg * 4;

    #pragma unroll 2
    for (int k4 = 0; k4 < H_DIM / 4; k4++) {
        const float4 Av0 = w0[k4], Av1 = w1[k4], Av2 = w2[k4], Av3 = w3[k4];
        QUAD_FMA(xp, k4);
    }

    // unpack & store: [t][b][n] float4 over n
    #pragma unroll
    for (int bp = 0; bp < 2; bp++) {
        float l0,h0,l1,h1,l2,h2,l3,h3;
        UNPK(l0,h0, acc0p[bp]); UNPK(l1,h1, acc1p[bp]);
        UNPK(l2,h2, acc2p[bp]); UNPK(l3,h3, acc3p[bp]);
        float4 vL; vL.x=l0; vL.y=l1; vL.z=l2; vL.w=l3;
        float4 vH; vH.x=h0; vH.y=h1; vH.z=h2; vH.w=h3;
        *reinterpret_cast<float4*>(g_bx + ((size_t)t * B_SZ + (bg*4 + 2*bp))     * N_DIM + n0) = vL;
        *reinterpret_cast<float4*>(g_bx + ((size_t)t * B_SZ + (bg*4 + 2*bp + 1)) * N_DIM + n0) = vH;
    }
}

// ---------------- SGEMM: Y = X @ X (512x512), 32x32 tiles, f32x2 -----------
__device__ __forceinline__ const float* mat_sel(const float* Aext, int s)
{
    if (s == 0) return Aext;
    if (s == 1) return g_P1;
    if (s == 2) return g_P2;
    return g_Mp + (size_t)(s - 10) * N_DIM * N_DIM;
}
__device__ __forceinline__ float* mat_sel_w(int s)
{
    if (s == 1) return g_P1;
    if (s == 2) return g_P2;
    return g_Mp + (size_t)(s - 10) * N_DIM * N_DIM;
}

__global__ __launch_bounds__(128) void matsq_kernel(const float* __restrict__ Aext,
                                                    int src_sel, int dst_sel)
{
    const float* __restrict__ X = mat_sel(Aext, src_sel);
    float* __restrict__ Y = mat_sel_w(dst_sel);

    __shared__ float As[32][34];   // [k][i] (34: keeps float2 8B-aligned)
    __shared__ float Bs[32][36];   // [k][j] (36: keeps float4 16B-aligned)
    const int tid = threadIdx.x;
    const int tx = tid & 7;        // j-group: 4 cols
    const int ty = tid >> 3;       // row-group: 2 rows
    const int i0 = blockIdx.y * 32, j0 = blockIdx.x * 32;

    u64 acc0[2] = {0,0}, acc1[2] = {0,0};

    const int lrow = tid >> 2;     // 0..31 for tile loads
    const int lq   = tid & 3;      // 0..3

    for (int kt = 0; kt < N_DIM; kt += 32) {
        // A tile -> As[k][i] transposed
        {
            const float4 v1 = *reinterpret_cast<const float4*>(X + (size_t)(i0 + lrow) * N_DIM + kt + lq * 8);
            const float4 v2 = *reinterpret_cast<const float4*>(X + (size_t)(i0 + lrow) * N_DIM + kt + lq * 8 + 4);
            As[lq*8 + 0][lrow] = v1.x; As[lq*8 + 1][lrow] = v1.y;
            As[lq*8 + 2][lrow] = v1.z; As[lq*8 + 3][lrow] = v1.w;
            As[lq*8 + 4][lrow] = v2.x; As[lq*8 + 5][lrow] = v2.y;
            As[lq*8 + 6][lrow] = v2.z; As[lq*8 + 7][lrow] = v2.w;
        }
        // B tile -> Bs[k][j]
        {
            const float4 v1 = *reinterpret_cast<const float4*>(X + (size_t)(kt + lrow) * N_DIM + j0 + lq * 8);
            const float4 v2 = *reinterpret_cast<const float4*>(X + (size_t)(kt + lrow) * N_DIM + j0 + lq * 8 + 4);
            *reinterpret_cast<float4*>(&Bs[lrow][lq*8])     = v1;
            *reinterpret_cast<float4*>(&Bs[lrow][lq*8 + 4]) = v2;
        }
        __syncthreads();

        #pragma unroll
        for (int kk = 0; kk < 32; kk++) {
            const float2 a = *reinterpret_cast<const float2*>(&As[kk][ty * 2]);
            const ulonglong2 bv = *reinterpret_cast<const ulonglong2*>(&Bs[kk][tx * 4]);
            u64 ap;
            PACK2(ap, a.x); FFMA2(acc0[0], ap, bv.x); FFMA2(acc0[1], ap, bv.y);
            PACK2(ap, a.y); FFMA2(acc1[0], ap, bv.x); FFMA2(acc1[1], ap, bv.y);
        }
        __syncthreads();
    }

    // epilogue
    {
        float l0,h0,l1,h1;
        UNPK(l0,h0, acc0[0]); UNPK(l1,h1, acc0[1]);
        float4 v; v.x=l0; v.y=h0; v.z=l1; v.w=h1;
        *reinterpret_cast<float4*>(Y + (size_t)(i0 + ty*2 + 0) * N_DIM + j0 + tx*4) = v;
        UNPK(l0,h0, acc1[0]); UNPK(l1,h1, acc1[1]);
        v.x=l0; v.y=h0; v.z=l1; v.w=h1;
        *reinterpret_cast<float4*>(Y + (size_t)(i0 + ty*2 + 1) * N_DIM + j0 + tx*4) = v;
    }
}

// ---------------- Kogge-Stone level: x'_c = M^(2^d) x_{c-2^d} + x_c --------
__device__ __forceinline__ const float* ks_sel(int s)
{
    if (s == 0) return g_f;
    return (s == 1) ? g_XA : g_XB;
}
__device__ __forceinline__ float* ks_sel_w(int s)
{
    return (s == 1) ? g_XA : g_XB;
}

__global__ __launch_bounds__(512) void ks_level_kernel(int d, int src_sel, int dst_sel)
{
    const float* __restrict__ src = ks_sel(src_sel);
    float* __restrict__ dst = ks_sel_w(dst_sel);
    const int c = blockIdx.x;
    const int shift = 1 << d;

    if (c < shift) {
        const int n = threadIdx.x;
        #pragma unroll
        for (int b = 0; b < B_SZ; b++)
            dst[((size_t)c * B_SZ + b) * N_DIM + n] = src[((size_t)c * B_SZ + b) * N_DIM + n];
        return;
    }

    __shared__ float xs[N_DIM * BPAD];         // x_{c-shift} as [k][b]
    const float* __restrict__ M = g_Mp + (size_t)d * N_DIM * N_DIM;
    const int bg = threadIdx.x & 3;
    const int rg = threadIdx.x >> 2;
    const int n0 = rg * 4;

    {
        const int k = threadIdx.x;
        const float* sp = src + (size_t)(c - shift) * B_SZ * N_DIM;
        #pragma unroll
        for (int b = 0; b < B_SZ; b++)
            xs[k * BPAD + b] = sp[(size_t)b * N_DIM + k];
    }
    __syncthreads();

    u64 acc0p[2], acc1p[2], acc2p[2], acc3p[2];
    #pragma unroll
    for (int bp = 0; bp < 2; bp++) {
        const float4 vL = *reinterpret_cast<const float4*>(
            src + ((size_t)c * B_SZ + (bg*4 + 2*bp))     * N_DIM + n0);
        const float4 vH = *reinterpret_cast<const float4*>(
            src + ((size_t)c * B_SZ + (bg*4 + 2*bp + 1)) * N_DIM + n0);
        PACKLOHI(acc0p[bp], vL.x, vH.x);
        PACKLOHI(acc1p[bp], vL.y, vH.y);
        PACKLOHI(acc2p[bp], vL.z, vH.z);
        PACKLOHI(acc3p[bp], vL.w, vH.w);
    }

    const float4* m0 = reinterpret_cast<const float4*>(M + (size_t)(n0 + 0) * N_DIM);
    const float4* m1 = reinterpret_cast<const float4*>(M + (size_t)(n0 + 1) * N_DIM);
    const float4* m2 = reinterpret_cast<const float4*>(M + (size_t)(n0 + 2) * N_DIM);
    const float4* m3 = reinterpret_cast<const float4*>(M + (size_t)(n0 + 3) * N_DIM);
    const float* xp = xs + bg * 4;

    #pragma unroll 2
    for (int k4 = 0; k4 < N_DIM / 4; k4++) {
        const float4 Av0 = m0[k4], Av1 = m1[k4], Av2 = m2[k4], Av3 = m3[k4];
        QUAD_FMA(xp, k4);
    }

    #pragma unroll
    for (int bp = 0; bp < 2; bp++) {
        float l0,h0,l1,h1,l2,h2,l3,h3;
        UNPK(l0,h0, acc0p[bp]); UNPK(l1,h1, acc1p[bp]);
        UNPK(l2,h2, acc2p[bp]); UNPK(l3,h3, acc3p[bp]);
        float4 vL; vL.x=l0; vL.y=l1; vL.z=l2; vL.w=l3;
        float4 vH; vH.x=h0; vH.y=h1; vH.z=h2; vH.w=h3;
        *reinterpret_cast<float4*>(dst + ((size_t)c * B_SZ + (bg*4 + 2*bp))     * N_DIM + n0) = vL;
        *reinterpret_cast<float4*>(dst + ((size_t)c * B_SZ + (bg*4 + 2*bp + 1)) * N_DIM + n0) = vH;
    }
}

// ---------------- Chunk scan kernels (one CTA per chunk) -------------------
template <bool FIRST_PASS>
__global__ __launch_bounds__(512) void scan_kernel(const float* __restrict__ A,
                                                   float* __restrict__ out,
                                                   int out_size)
{
    __shared__ float hs[N_DIM * BPAD];         // 40 KB, [k][b]
    const int c  = blockIdx.x;
    const int bg = threadIdx.x & 3;
    const int rg = threadIdx.x >> 2;
    const int n0 = rg * 4;

    // init h_in
    if (FIRST_PASS || c == 0) {
        #pragma unroll
        for (int rr = 0; rr < 4; rr++)
            #pragma unroll
            for (int bb = 0; bb < 4; bb++)
                hs[(n0 + rr) * BPAD + bg*4 + bb] = 0.0f;
    } else {
        // entry state = KS result of chunk c-1 (inclusive scan)
        #pragma unroll
        for (int bb = 0; bb < 4; bb++) {
            const float4 v = *reinterpret_cast<const float4*>(
                g_XA + ((size_t)(c - 1) * B_SZ + (bg*4 + bb)) * N_DIM + n0);
            hs[(n0 + 0) * BPAD + bg*4 + bb] = v.x;
            hs[(n0 + 1) * BPAD + bg*4 + bb] = v.y;
            hs[(n0 + 2) * BPAD + bg*4 + bb] = v.z;
            hs[(n0 + 3) * BPAD + bg*4 + bb] = v.w;
        }
    }
    __syncthreads();

    const float4* a0 = reinterpret_cast<const float4*>(A + (size_t)(n0 + 0) * N_DIM);
    const float4* a1 = reinterpret_cast<const float4*>(A + (size_t)(n0 + 1) * N_DIM);
    const float4* a2 = reinterpret_cast<const float4*>(A + (size_t)(n0 + 2) * N_DIM);
    const float4* a3 = reinterpret_cast<const float4*>(A + (size_t)(n0 + 3) * N_DIM);
    const float* hp = hs + bg * 4;

    u64 acc0p[2], acc1p[2], acc2p[2], acc3p[2];

    for (int j = 0; j < T_CH; j++) {
        const int t = c * T_CH + j;

        // acc = bx[t][b][n0..n0+3], packed over batch pairs
        #pragma unroll
        for (int bp = 0; bp < 2; bp++) {
            const float4 vL = *reinterpret_cast<const float4*>(
                g_bx + ((size_t)t * B_SZ + (bg*4 + 2*bp))     * N_DIM + n0);
            const float4 vH = *reinterpret_cast<const float4*>(
                g_bx + ((size_t)t * B_SZ + (bg*4 + 2*bp + 1)) * N_DIM + n0);
            PACKLOHI(acc0p[bp], vL.x, vH.x);
            PACKLOHI(acc1p[bp], vL.y, vH.y);
            PACKLOHI(acc2p[bp], vL.z, vH.z);
            PACKLOHI(acc3p[bp], vL.w, vH.w);
        }

        #pragma unroll 2
        for (int k4 = 0; k4 < N_DIM / 4; k4++) {
            const float4 Av0 = a0[k4], Av1 = a1[k4], Av2 = a2[k4], Av3 = a3[k4];
            QUAD_FMA(hp, k4);
        }

        __syncthreads();   // all reads of old h done

        // publish h_new: row-major n, batch minor — packed pairs store directly
        {
            ulonglong2 s;
            s.x = acc0p[0]; s.y = acc0p[1];
            *reinterpret_cast<ulonglong2*>(hs + (n0 + 0) * BPAD + bg*4) = s;
            s.x = acc1p[0]; s.y = acc1p[1];
            *reinterpret_cast<ulonglong2*>(hs + (n0 + 1) * BPAD + bg*4) = s;
            s.x = acc2p[0]; s.y = acc2p[1];
            *reinterpret_cast<ulonglong2*>(hs + (n0 + 2) * BPAD + bg*4) = s;
            s.x = acc3p[0]; s.y = acc3p[1];
            *reinterpret_cast<ulonglong2*>(hs + (n0 + 3) * BPAD + bg*4) = s;
        }

        if (!FIRST_PASS) {
            #pragma unroll
            for (int bp = 0; bp < 2; bp++) {
                float l0,h0,l1,h1,l2,h2,l3,h3;
                UNPK(l0,h0, acc0p[bp]); UNPK(l1,h1, acc1p[bp]);
                UNPK(l2,h2, acc2p[bp]); UNPK(l3,h3, acc3p[bp]);
                float4 vL; vL.x=l0; vL.y=l1; vL.z=l2; vL.w=l3;
                float4 vH; vH.x=h0; vH.y=h1; vH.z=h2; vH.w=h3;
                *reinterpret_cast<float4*>(
                    out + ((size_t)(bg*4 + 2*bp)     * L_LEN + t) * N_DIM + n0) = vL;
                *reinterpret_cast<float4*>(
                    out + ((size_t)(bg*4 + 2*bp + 1) * L_LEN + t) * N_DIM + n0) = vH;
            }
        }
        __syncthreads();   // h_new visible
    }

    if (FIRST_PASS) {
        #pragma unroll
        for (int bp = 0; bp < 2; bp++) {
            float l0,h0,l1,h1,l2,h2,l3,h3;
            UNPK(l0,h0, acc0p[bp]); UNPK(l1,h1, acc1p[bp]);
            UNPK(l2,h2, acc2p[bp]); UNPK(l3,h3, acc3p[bp]);
            float4 vL; vL.x=l0; vL.y=l1; vL.z=l2; vL.w=l3;
            float4 vH; vH.x=h0; vH.y=h1; vH.z=h2; vH.w=h3;
            *reinterpret_cast<float4*>(
                g_f + ((size_t)c * B_SZ + (bg*4 + 2*bp))     * N_DIM + n0) = vL;
            *reinterpret_cast<float4*>(
                g_f + ((size_t)c * B_SZ + (bg*4 + 2*bp + 1)) * N_DIM + n0) = vH;
        }
    } else if (c == C_CH - 1 && out_size >= OUT_MAIN + N_DIM * B_SZ) {
        // h_final in (N, B) layout appended after main output
        #pragma unroll
        for (int bp = 0; bp < 2; bp++) {
            float l0,h0,l1,h1,l2,h2,l3,h3;
            UNPK(l0,h0, acc0p[bp]); UNPK(l1,h1, acc1p[bp]);
            UNPK(l2,h2, acc2p[bp]); UNPK(l3,h3, acc3p[bp]);
            out[OUT_MAIN + (size_t)(n0 + 0) * B_SZ + (bg*4 + 2*bp)]     = l0;
            out[OUT_MAIN + (size_t)(n0 + 0) * B_SZ + (bg*4 + 2*bp + 1)] = h0;
            out[OUT_MAIN + (size_t)(n0 + 1) * B_SZ + (bg*4 + 2*bp)]     = l1;
            out[OUT_MAIN + (size_t)(n0 + 1) * B_SZ + (bg*4 + 2*bp + 1)] = h1;
            out[OUT_MAIN + (size_t)(n0 + 2) * B_SZ + (bg*4 + 2*bp)]     = l2;
            out[OUT_MAIN + (size_t)(n0 + 2) * B_SZ + (bg*4 + 2*bp + 1)] = h2;
            out[OUT_MAIN + (size_t)(n0 + 3) * B_SZ + (bg*4 + 2*bp)]     = l3;
            out[OUT_MAIN + (size_t)(n0 + 3) * B_SZ + (bg*4 + 2*bp + 1)] = h3;
        }
    }
}

// ---------------- launch ----------------------------------------------------
extern "C" void kernel_launch(void* const* d_in, const int* in_sizes, int n_in,
                              void* d_out, int out_size)
{
    const float* x  = (const float*)d_in[0];   // (B, L, H)
    const float* A  = (const float*)d_in[1];   // (N, N)
    const float* Bm = (const float*)d_in[2];   // (N, H)
    float* out = (float*)d_out;

    dim3 sgrid(N_DIM / 32, N_DIM / 32);        // 16x16 = 256 CTAs

    // launches #1-#4: A^2, A^4, A^8, Mp[0]=A^16   (independent of proj/scan1)
    matsq_kernel<<<sgrid, 128>>>(A, 0, 1);
    matsq_kernel<<<sgrid, 128>>>(A, 1, 2);
    matsq_kernel<<<sgrid, 128>>>(A, 2, 1);
    matsq_kernel<<<sgrid, 128>>>(A, 1, 10);

    // launch #5: input projection -> g_bx[t][b][n]
    proj_kernel<<<L_LEN, 512>>>(x, Bm);

    // launch #6: local chunk scans (zero init) -> g_f   [ncu -s 5 profiles this]
    scan_kernel<true><<<C_CH, 512>>>(A, nullptr, 0);

    // remaining matrix powers Mp[d] = M^(2^d)
    matsq_kernel<<<sgrid, 128>>>(A, 10, 11);
    matsq_kernel<<<sgrid, 128>>>(A, 11, 12);
    matsq_kernel<<<sgrid, 128>>>(A, 12, 13);
    matsq_kernel<<<sgrid, 128>>>(A, 13, 14);
    matsq_kernel<<<sgrid, 128>>>(A, 14, 15);
    matsq_kernel<<<sgrid, 128>>>(A, 15, 16);

    // Kogge-Stone scan over chunk finals (7 levels, graph-edge sync)
    ks_level_kernel<<<C_CH, 512>>>(0, 0, 1);
    ks_level_kernel<<<C_CH, 512>>>(1, 1, 2);
    ks_level_kernel<<<C_CH, 512>>>(2, 2, 1);
    ks_level_kernel<<<C_CH, 512>>>(3, 1, 2);
    ks_level_kernel<<<C_CH, 512>>>(4, 2, 1);
    ks_level_kernel<<<C_CH, 512>>>(5, 1, 2);
    ks_level_kernel<<<C_CH, 512>>>(6, 2, 1);   // final in XA

    // true chunk scans from XA[c-1], writing outputs (+ h_final)
    scan_kernel<false><<<C_CH, 512>>>(A, out, out_size);
}

// round 8
// speedup vs baseline: 1.2190x; 1.0076x over previous
#include <cuda_runtime.h>

// Problem constants
#define B_SZ    16
#define L_LEN   2048
#define H_DIM   512
#define N_DIM   512
#define T_CH    16                 // chunk length
#define C_CH    (L_LEN / T_CH)     // 128 chunks
#define OUT_MAIN (B_SZ * L_LEN * N_DIM)
#define BPAD    20                 // proj smem pad (floats)

// scan_tf32 smem geometry (floats)
#define ASTR    12                 // A-slab row stride: 8 k + 4 pad
#define SLABF   (N_DIM * ASTR)     // 6144 floats = 24 KB per (buf,split)
#define H1_OFF  (4 * SLABF)        // 24576
#define HSTR    24                 // h row stride
#define H2_OFF  (H1_OFF + N_DIM * HSTR)            // 36864
#define SMEM_FLOATS (H2_OFF + N_DIM * HSTR)        // 49152
#define SCAN_SMEM_BYTES (SMEM_FLOATS * 4)          // 196608

// ---------------- scratch (device globals; no allocations allowed) ----------
__device__ float g_bx[L_LEN * N_DIM * B_SZ];   // Bx projections  [t][n][b]  (64MB)
__device__ float g_f [C_CH * B_SZ * N_DIM];    // chunk local finals [c][b][n]
__device__ float g_XA[C_CH * B_SZ * N_DIM];    // Kogge-Stone ping
__device__ float g_XB[C_CH * B_SZ * N_DIM];    // Kogge-Stone pong
__device__ float g_P1[N_DIM * N_DIM];
__device__ float g_P2[N_DIM * N_DIM];
__device__ float g_Mp[7 * N_DIM * N_DIM];      // M^(2^d), M = A^16, d=0..6
__device__ float g_A1t[N_DIM * N_DIM];         // tf32 hi split, [k8][row][8] blocked
__device__ float g_A2t[N_DIM * N_DIM];         // tf32 lo split, same layout

// ---------------- tf32 helpers ----------------------------------------------
// NOTE: cvt with tf32 dst requires a .b32 register destination (PTX spec);
// the resulting bit pattern is a valid fp32 value (low mantissa bits zeroed).
__device__ __forceinline__ float tf32r(float x)
{
    unsigned y;
    asm("cvt.rna.tf32.f32 %0, %1;" : "=r"(y) : "f"(x));
    return __uint_as_float(y);
}

#define MMATF32(d, a, b) \
    asm volatile("mma.sync.aligned.m16n8k8.row.col.f32.tf32.tf32.f32 " \
        "{%0,%1,%2,%3}, {%4,%5,%6,%7}, {%8,%9}, {%0,%1,%2,%3};" \
        : "+f"((d)[0]), "+f"((d)[1]), "+f"((d)[2]), "+f"((d)[3]) \
        : "r"((a)[0]), "r"((a)[1]), "r"((a)[2]), "r"((a)[3]), \
          "r"((b)[0]), "r"((b)[1]))

// ---------------- packed fp32x2 (proj / matsq) -------------------------------
typedef unsigned long long u64;
#define FFMA2(acc, apk, hpk) \
    asm("fma.rn.f32x2 %0, %1, %2, %0;" : "+l"(acc) : "l"(apk), "l"(hpk))
#define PACK2(dst, f) \
    asm("mov.b64 %0, {%1, %1};" : "=l"(dst) : "f"(f))
#define UNPK(lo, hi, src) \
    asm("mov.b64 {%0, %1}, %2;" : "=f"(lo), "=f"(hi) : "l"(src))

#define ONEK(base, off, c0, c1, c2, c3) do {                                   \
    const ulonglong2 hvp = *reinterpret_cast<const ulonglong2*>((base) + (off) * BPAD); \
    u64 ap;                                                                    \
    PACK2(ap, c0); FFMA2(acc0p[0], ap, hvp.x); FFMA2(acc0p[1], ap, hvp.y);     \
    PACK2(ap, c1); FFMA2(acc1p[0], ap, hvp.x); FFMA2(acc1p[1], ap, hvp.y);     \
    PACK2(ap, c2); FFMA2(acc2p[0], ap, hvp.x); FFMA2(acc2p[1], ap, hvp.y);     \
    PACK2(ap, c3); FFMA2(acc3p[0], ap, hvp.x); FFMA2(acc3p[1], ap, hvp.y);     \
} while (0)

#define QUAD_FMA(base, k4) do {                                                \
    ONEK(base, 4*(k4) + 0, Av0.x, Av1.x, Av2.x, Av3.x);                        \
    ONEK(base, 4*(k4) + 1, Av0.y, Av1.y, Av2.y, Av3.y);                        \
    ONEK(base, 4*(k4) + 2, Av0.z, Av1.z, Av2.z, Av3.z);                        \
    ONEK(base, 4*(k4) + 3, Av0.w, Av1.w, Av2.w, Av3.w);                        \
} while (0)

// ---------------- prep: A (fp32) -> tf32 split, k8-blocked ------------------
__global__ __launch_bounds__(256) void prep_kernel(const float* __restrict__ A)
{
    const int idx = blockIdx.x * 256 + threadIdx.x;      // 262144 total
    const int row = idx >> 9;
    const int k   = idx & 511;
    const int kc  = k >> 3, kk = k & 7;
    const float a = A[idx];
    const float a1 = tf32r(a);
    const float a2 = tf32r(a - a1);
    const int dst = kc * (N_DIM * 8) + row * 8 + kk;
    g_A1t[dst] = a1;
    g_A2t[dst] = a2;
}

// ---------------- Phase 1: bx[t][n][b] = sum_h Bm[n][h] * x[b][t][h] -------
__global__ __launch_bounds__(512) void proj_kernel(const float* __restrict__ x,
                                                   const float* __restrict__ Bm)
{
    __shared__ float xs[H_DIM * BPAD];         // [h][b], 40 KB
    const int t  = blockIdx.x;
    const int bg = threadIdx.x & 3;
    const int rg = threadIdx.x >> 2;

    {
        const int k = threadIdx.x;
        #pragma unroll
        for (int b = 0; b < B_SZ; b++)
            xs[k * BPAD + b] = x[((size_t)b * L_LEN + t) * H_DIM + k];
    }
    __syncthreads();

    u64 acc0p[2] = {0,0}, acc1p[2] = {0,0}, acc2p[2] = {0,0}, acc3p[2] = {0,0};

    const int n0 = rg * 4;
    const float4* w0 = reinterpret_cast<const float4*>(Bm + (size_t)(n0 + 0) * H_DIM);
    const float4* w1 = reinterpret_cast<const float4*>(Bm + (size_t)(n0 + 1) * H_DIM);
    const float4* w2 = reinterpret_cast<const float4*>(Bm + (size_t)(n0 + 2) * H_DIM);
    const float4* w3 = reinterpret_cast<const float4*>(Bm + (size_t)(n0 + 3) * H_DIM);
    const float* xp = xs + bg * 4;

    #pragma unroll 2
    for (int k4 = 0; k4 < H_DIM / 4; k4++) {
        const float4 Av0 = w0[k4], Av1 = w1[k4], Av2 = w2[k4], Av3 = w3[k4];
        QUAD_FMA(xp, k4);
    }

    // store [t][n][b]
    {
        float l0,h0,l1,h1;
        float4 v;
        UNPK(l0,h0, acc0p[0]); UNPK(l1,h1, acc0p[1]);
        v.x=l0; v.y=h0; v.z=l1; v.w=h1;
        *reinterpret_cast<float4*>(g_bx + ((size_t)t * N_DIM + n0 + 0) * B_SZ + bg*4) = v;
        UNPK(l0,h0, acc1p[0]); UNPK(l1,h1, acc1p[1]);
        v.x=l0; v.y=h0; v.z=l1; v.w=h1;
        *reinterpret_cast<float4*>(g_bx + ((size_t)t * N_DIM + n0 + 1) * B_SZ + bg*4) = v;
        UNPK(l0,h0, acc2p[0]); UNPK(l1,h1, acc2p[1]);
        v.x=l0; v.y=h0; v.z=l1; v.w=h1;
        *reinterpret_cast<float4*>(g_bx + ((size_t)t * N_DIM + n0 + 2) * B_SZ + bg*4) = v;
        UNPK(l0,h0, acc3p[0]); UNPK(l1,h1, acc3p[1]);
        v.x=l0; v.y=h0; v.z=l1; v.w=h1;
        *reinterpret_cast<float4*>(g_bx + ((size_t)t * N_DIM + n0 + 3) * B_SZ + bg*4) = v;
    }
}

// ---------------- SGEMM: Y = X @ X (512x512), 32x32 tiles -------------------
__device__ __forceinline__ const float* mat_sel(const float* Aext, int s)
{
    if (s == 0) return Aext;
    if (s == 1) return g_P1;
    if (s == 2) return g_P2;
    return g_Mp + (size_t)(s - 10) * N_DIM * N_DIM;
}
__device__ __forceinline__ float* mat_sel_w(int s)
{
    if (s == 1) return g_P1;
    if (s == 2) return g_P2;
    return g_Mp + (size_t)(s - 10) * N_DIM * N_DIM;
}

__global__ __launch_bounds__(128) void matsq_kernel(const float* __restrict__ Aext,
                                                    int src_sel, int dst_sel)
{
    const float* __restrict__ X = mat_sel(Aext, src_sel);
    float* __restrict__ Y = mat_sel_w(dst_sel);

    __shared__ float As[32][34];
    __shared__ float Bs[32][36];
    const int tid = threadIdx.x;
    const int tx = tid & 7;
    const int ty = tid >> 3;
    const int i0 = blockIdx.y * 32, j0 = blockIdx.x * 32;

    u64 acc0[2] = {0,0}, acc1[2] = {0,0};

    const int lrow = tid >> 2;
    const int lq   = tid & 3;

    for (int kt = 0; kt < N_DIM; kt += 32) {
        {
            const float4 v1 = *reinterpret_cast<const float4*>(X + (size_t)(i0 + lrow) * N_DIM + kt + lq * 8);
            const float4 v2 = *reinterpret_cast<const float4*>(X + (size_t)(i0 + lrow) * N_DIM + kt + lq * 8 + 4);
            As[lq*8 + 0][lrow] = v1.x; As[lq*8 + 1][lrow] = v1.y;
            As[lq*8 + 2][lrow] = v1.z; As[lq*8 + 3][lrow] = v1.w;
            As[lq*8 + 4][lrow] = v2.x; As[lq*8 + 5][lrow] = v2.y;
            As[lq*8 + 6][lrow] = v2.z; As[lq*8 + 7][lrow] = v2.w;
        }
        {
            const float4 v1 = *reinterpret_cast<const float4*>(X + (size_t)(kt + lrow) * N_DIM + j0 + lq * 8);
            const float4 v2 = *reinterpret_cast<const float4*>(X + (size_t)(kt + lrow) * N_DIM + j0 + lq * 8 + 4);
            *reinterpret_cast<float4*>(&Bs[lrow][lq*8])     = v1;
            *reinterpret_cast<float4*>(&Bs[lrow][lq*8 + 4]) = v2;
        }
        __syncthreads();

        #pragma unroll
        for (int kk = 0; kk < 32; kk++) {
            const float2 a = *reinterpret_cast<const float2*>(&As[kk][ty * 2]);
            const ulonglong2 bv = *reinterpret_cast<const ulonglong2*>(&Bs[kk][tx * 4]);
            u64 ap;
            PACK2(ap, a.x); FFMA2(acc0[0], ap, bv.x); FFMA2(acc0[1], ap, bv.y);
            PACK2(ap, a.y); FFMA2(acc1[0], ap, bv.x); FFMA2(acc1[1], ap, bv.y);
        }
        __syncthreads();
    }

    {
        float l0,h0,l1,h1;
        UNPK(l0,h0, acc0[0]); UNPK(l1,h1, acc0[1]);
        float4 v; v.x=l0; v.y=h0; v.z=l1; v.w=h1;
        *reinterpret_cast<float4*>(Y + (size_t)(i0 + ty*2 + 0) * N_DIM + j0 + tx*4) = v;
        UNPK(l0,h0, acc1[0]); UNPK(l1,h1, acc1[1]);
        v.x=l0; v.y=h0; v.z=l1; v.w=h1;
        *reinterpret_cast<float4*>(Y + (size_t)(i0 + ty*2 + 1) * N_DIM + j0 + tx*4) = v;
    }
}

// ---------------- Kogge-Stone level: x'_c = M^(2^d) x_{c-2^d} + x_c --------
__device__ __forceinline__ const float* ks_sel(int s)
{
    if (s == 0) return g_f;
    return (s == 1) ? g_XA : g_XB;
}
__device__ __forceinline__ float* ks_sel_w(int s)
{
    return (s == 1) ? g_XA : g_XB;
}

__global__ __launch_bounds__(512) void ks_level_kernel(int d, int src_sel, int dst_sel)
{
    const float* __restrict__ src = ks_sel(src_sel);
    float* __restrict__ dst = ks_sel_w(dst_sel);
    const int c = blockIdx.x;
    const int shift = 1 << d;

    if (c < shift) {
        const int n = threadIdx.x;
        #pragma unroll
        for (int b = 0; b < B_SZ; b++)
            dst[((size_t)c * B_SZ + b) * N_DIM + n] = src[((size_t)c * B_SZ + b) * N_DIM + n];
        return;
    }

    __shared__ float xs[N_DIM * BPAD];         // x_{c-shift} as [k][b]
    const float* __restrict__ M = g_Mp + (size_t)d * N_DIM * N_DIM;
    const int bg = threadIdx.x & 3;
    const int rg = threadIdx.x >> 2;
    const int n0 = rg * 4;

    {
        const int k = threadIdx.x;
        const float* sp = src + (size_t)(c - shift) * B_SZ * N_DIM;
        #pragma unroll
        for (int b = 0; b < B_SZ; b++)
            xs[k * BPAD + b] = sp[(size_t)b * N_DIM + k];
    }
    __syncthreads();

    float acc0[4], acc1[4], acc2[4], acc3[4];
    #pragma unroll
    for (int bb = 0; bb < 4; bb++) {
        const float4 v = *reinterpret_cast<const float4*>(
            src + ((size_t)c * B_SZ + (bg*4 + bb)) * N_DIM + n0);
        acc0[bb] = v.x; acc1[bb] = v.y; acc2[bb] = v.z; acc3[bb] = v.w;
    }

    const float4* m0 = reinterpret_cast<const float4*>(M + (size_t)(n0 + 0) * N_DIM);
    const float4* m1 = reinterpret_cast<const float4*>(M + (size_t)(n0 + 1) * N_DIM);
    const float4* m2 = reinterpret_cast<const float4*>(M + (size_t)(n0 + 2) * N_DIM);
    const float4* m3 = reinterpret_cast<const float4*>(M + (size_t)(n0 + 3) * N_DIM);
    const float* xp = xs + bg * 4;

    #pragma unroll 2
    for (int k4 = 0; k4 < N_DIM / 4; k4++) {
        const float4 Av0 = m0[k4], Av1 = m1[k4], Av2 = m2[k4], Av3 = m3[k4];
        const int k = 4 * k4;
        #pragma unroll
        for (int kk = 0; kk < 4; kk++) {
            const float a0v = (&Av0.x)[kk], a1v = (&Av1.x)[kk],
                        a2v = (&Av2.x)[kk], a3v = (&Av3.x)[kk];
            const float4 hv = *reinterpret_cast<const float4*>(xp + (k + kk) * BPAD);
            acc0[0] += a0v*hv.x; acc0[1] += a0v*hv.y; acc0[2] += a0v*hv.z; acc0[3] += a0v*hv.w;
            acc1[0] += a1v*hv.x; acc1[1] += a1v*hv.y; acc1[2] += a1v*hv.z; acc1[3] += a1v*hv.w;
            acc2[0] += a2v*hv.x; acc2[1] += a2v*hv.y; acc2[2] += a2v*hv.z; acc2[3] += a2v*hv.w;
            acc3[0] += a3v*hv.x; acc3[1] += a3v*hv.y; acc3[2] += a3v*hv.z; acc3[3] += a3v*hv.w;
        }
    }

    #pragma unroll
    for (int bb = 0; bb < 4; bb++) {
        float4 v; v.x = acc0[bb]; v.y = acc1[bb]; v.z = acc2[bb]; v.w = acc3[bb];
        *reinterpret_cast<float4*>(
            dst + ((size_t)c * B_SZ + (bg*4 + bb)) * N_DIM + n0) = v;
    }
}

// ---------------- tf32 chunk scan (one CTA per chunk) ------------------------
// h in smem as fp32 tf32-rounded split (h1 + h2); A streamed as tf32 split.
// Fragment layouts per PTX ISA (m16n8k8.tf32):
//   A: a0=(row g,   col t), a1=(row g+8, col t), a2=(g, t+4), a3=(g+8, t+4)
//   B: b0=(row t,   col g), b1=(row t+4, col g)           [row=k, col=batch]
//   C: c0,c1=(row g, cols 2t,2t+1), c2,c3=(row g+8, same)
template <bool FIRST_PASS>
__global__ __launch_bounds__(512) void scan_tf32_kernel(float* __restrict__ out,
                                                        int out_size)
{
    extern __shared__ float smf[];
    float* h1s = smf + H1_OFF;
    float* h2s = smf + H2_OFF;

    const int c    = blockIdx.x;
    const int tid  = threadIdx.x;
    const int warp = tid >> 5;
    const int lane = tid & 31;
    const int g    = lane >> 2;          // groupID 0..7
    const int t    = lane & 3;           // threadID_in_group 0..3
    const int row0 = warp * 32;          // warp owns output rows [row0, row0+32)

    // ---- init h split ----
    if (FIRST_PASS || c == 0) {
        #pragma unroll
        for (int b = 0; b < B_SZ; b++) {
            h1s[tid * HSTR + b] = 0.0f;
            h2s[tid * HSTR + b] = 0.0f;
        }
    } else {
        const float* sp = g_XA + (size_t)(c - 1) * B_SZ * N_DIM;
        #pragma unroll
        for (int b = 0; b < B_SZ; b++) {
            const float v  = sp[(size_t)b * N_DIM + tid];
            const float v1 = tf32r(v);
            h1s[tid * HSTR + b] = v1;
            h2s[tid * HSTR + b] = tf32r(v - v1);
        }
    }
    __syncthreads();

    for (int j = 0; j < T_CH; j++) {
        const int tt = c * T_CH + j;

        // ---- acc init from bx[t][n][b] per C-fragment layout ----
        float acc[2][2][4];
        #pragma unroll
        for (int mt = 0; mt < 2; mt++) {
            const int n = row0 + mt * 16 + g;
            #pragma unroll
            for (int nt = 0; nt < 2; nt++) {
                const int b = nt * 8 + t * 2;
                const float2 vlo = *reinterpret_cast<const float2*>(
                    g_bx + ((size_t)tt * N_DIM + n) * B_SZ + b);
                const float2 vhi = *reinterpret_cast<const float2*>(
                    g_bx + ((size_t)tt * N_DIM + n + 8) * B_SZ + b);
                acc[mt][nt][0] = vlo.x; acc[mt][nt][1] = vlo.y;
                acc[mt][nt][2] = vhi.x; acc[mt][nt][3] = vhi.y;
            }
        }

        // ---- preload A slab 0 (both splits) ----
        {
            const float4* s1 = reinterpret_cast<const float4*>(g_A1t + tid * 8);
            const float4* s2 = reinterpret_cast<const float4*>(g_A2t + tid * 8);
            float4 p1 = s1[0], q1 = s1[1], p2 = s2[0], q2 = s2[1];
            float4* d1 = reinterpret_cast<float4*>(smf + tid * ASTR);
            float4* d2 = reinterpret_cast<float4*>(smf + SLABF + tid * ASTR);
            d1[0] = p1; d1[1] = q1;
            d2[0] = p2; d2[1] = q2;
        }
        __syncthreads();

        // ---- k loop: 64 chunks of k=8, double-buffered A slabs ----
        #pragma unroll 2
        for (int kc = 0; kc < 64; kc++) {
            float4 p1, q1, p2, q2;
            const bool more = (kc + 1 < 64);
            if (more) {
                const float4* s1 = reinterpret_cast<const float4*>(
                    g_A1t + (size_t)(kc + 1) * (N_DIM * 8) + tid * 8);
                const float4* s2 = reinterpret_cast<const float4*>(
                    g_A2t + (size_t)(kc + 1) * (N_DIM * 8) + tid * 8);
                p1 = s1[0]; q1 = s1[1]; p2 = s2[0]; q2 = s2[1];
            }

            const float* Ab1 = smf + (kc & 1) * (2 * SLABF);
            const float* Ab2 = Ab1 + SLABF;

            unsigned a1f[2][4], a2f[2][4];
            #pragma unroll
            for (int mt = 0; mt < 2; mt++) {
                const int rb = row0 + mt * 16;
                a1f[mt][0] = __float_as_uint(Ab1[(rb + g    ) * ASTR + t    ]);
                a1f[mt][1] = __float_as_uint(Ab1[(rb + g + 8) * ASTR + t    ]);
                a1f[mt][2] = __float_as_uint(Ab1[(rb + g    ) * ASTR + t + 4]);
                a1f[mt][3] = __float_as_uint(Ab1[(rb + g + 8) * ASTR + t + 4]);
                a2f[mt][0] = __float_as_uint(Ab2[(rb + g    ) * ASTR + t    ]);
                a2f[mt][1] = __float_as_uint(Ab2[(rb + g + 8) * ASTR + t    ]);
                a2f[mt][2] = __float_as_uint(Ab2[(rb + g    ) * ASTR + t + 4]);
                a2f[mt][3] = __float_as_uint(Ab2[(rb + g + 8) * ASTR + t + 4]);
            }

            const int kr = kc * 8;
            unsigned b1f[2][2], b2f[2][2];
            #pragma unroll
            for (int nt = 0; nt < 2; nt++) {
                const int col = nt * 8 + g;
                b1f[nt][0] = __float_as_uint(h1s[(kr + t    ) * HSTR + col]);
                b1f[nt][1] = __float_as_uint(h1s[(kr + t + 4) * HSTR + col]);
                b2f[nt][0] = __float_as_uint(h2s[(kr + t    ) * HSTR + col]);
                b2f[nt][1] = __float_as_uint(h2s[(kr + t + 4) * HSTR + col]);
            }

            #pragma unroll
            for (int mt = 0; mt < 2; mt++) {
                #pragma unroll
                for (int nt = 0; nt < 2; nt++) {
                    MMATF32(acc[mt][nt], a1f[mt], b1f[nt]);
                    MMATF32(acc[mt][nt], a1f[mt], b2f[nt]);
                    MMATF32(acc[mt][nt], a2f[mt], b1f[nt]);
                }
            }

            if (more) {
                float4* d1 = reinterpret_cast<float4*>(
                    smf + ((kc + 1) & 1) * (2 * SLABF) + tid * ASTR);
                float4* d2 = reinterpret_cast<float4*>(
                    smf + ((kc + 1) & 1) * (2 * SLABF) + SLABF + tid * ASTR);
                d1[0] = p1; d1[1] = q1;
                d2[0] = p2; d2[1] = q2;
            }
            __syncthreads();
        }

        // ---- write-back: h split (tf32-rounded), outputs, finals ----
        #pragma unroll
        for (int mt = 0; mt < 2; mt++) {
            #pragma unroll
            for (int nt = 0; nt < 2; nt++) {
                const int b = nt * 8 + t * 2;
                #pragma unroll
                for (int hh = 0; hh < 2; hh++) {
                    const int n = row0 + mt * 16 + g + hh * 8;
                    const float v0 = acc[mt][nt][hh * 2 + 0];
                    const float v1 = acc[mt][nt][hh * 2 + 1];
                    const float p0 = tf32r(v0), p1v = tf32r(v1);
                    h1s[n * HSTR + b]     = p0;
                    h1s[n * HSTR + b + 1] = p1v;
                    h2s[n * HSTR + b]     = tf32r(v0 - p0);
                    h2s[n * HSTR + b + 1] = tf32r(v1 - p1v);

                    if (!FIRST_PASS) {
                        out[((size_t)(b)     * L_LEN + tt) * N_DIM + n] = v0;
                        out[((size_t)(b + 1) * L_LEN + tt) * N_DIM + n] = v1;
                    }
                    if (FIRST_PASS && j == T_CH - 1) {
                        g_f[((size_t)c * B_SZ + b)     * N_DIM + n] = v0;
                        g_f[((size_t)c * B_SZ + b + 1) * N_DIM + n] = v1;
                    }
                    if (!FIRST_PASS && c == C_CH - 1 && j == T_CH - 1 &&
                        out_size >= OUT_MAIN + N_DIM * B_SZ) {
                        out[OUT_MAIN + (size_t)n * B_SZ + b]     = v0;
                        out[OUT_MAIN + (size_t)n * B_SZ + b + 1] = v1;
                    }
                }
            }
        }
        __syncthreads();
    }
}

// ---------------- launch ----------------------------------------------------
extern "C" void kernel_launch(void* const* d_in, const int* in_sizes, int n_in,
                              void* d_out, int out_size)
{
    const float* x  = (const float*)d_in[0];   // (B, L, H)
    const float* A  = (const float*)d_in[1];   // (N, N)
    const float* Bm = (const float*)d_in[2];   // (N, H)
    float* out = (float*)d_out;

    cudaFuncSetAttribute(scan_tf32_kernel<true>,
                         cudaFuncAttributeMaxDynamicSharedMemorySize, SCAN_SMEM_BYTES);
    cudaFuncSetAttribute(scan_tf32_kernel<false>,
                         cudaFuncAttributeMaxDynamicSharedMemorySize, SCAN_SMEM_BYTES);

    dim3 sgrid(N_DIM / 32, N_DIM / 32);

    // #1 prep, #2 proj, #3-#5 matsq, #6 scan1 (ncu -s 5 profiles #6)
    prep_kernel<<<N_DIM * N_DIM / 256, 256>>>(A);
    proj_kernel<<<L_LEN, 512>>>(x, Bm);
    matsq_kernel<<<sgrid, 128>>>(A, 0, 1);                     // P1 = A^2
    matsq_kernel<<<sgrid, 128>>>(A, 1, 2);                     // P2 = A^4
    matsq_kernel<<<sgrid, 128>>>(A, 2, 1);                     // P1 = A^8
    scan_tf32_kernel<true><<<C_CH, 512, SCAN_SMEM_BYTES>>>(nullptr, 0);

    matsq_kernel<<<sgrid, 128>>>(A, 1, 10);                    // Mp[0] = A^16
    matsq_kernel<<<sgrid, 128>>>(A, 10, 11);                   // A^32
    matsq_kernel<<<sgrid, 128>>>(A, 11, 12);                   // A^64
    matsq_kernel<<<sgrid, 128>>>(A, 12, 13);                   // A^128
    matsq_kernel<<<sgrid, 128>>>(A, 13, 14);                   // A^256
    matsq_kernel<<<sgrid, 128>>>(A, 14, 15);                   // A^512
    matsq_kernel<<<sgrid, 128>>>(A, 15, 16);                   // A^1024

    ks_level_kernel<<<C_CH, 512>>>(0, 0, 1);
    ks_level_kernel<<<C_CH, 512>>>(1, 1, 2);
    ks_level_kernel<<<C_CH, 512>>>(2, 2, 1);
    ks_level_kernel<<<C_CH, 512>>>(3, 1, 2);
    ks_level_kernel<<<C_CH, 512>>>(4, 2, 1);
    ks_level_kernel<<<C_CH, 512>>>(5, 1, 2);
    ks_level_kernel<<<C_CH, 512>>>(6, 2, 1);   // final in XA

    scan_tf32_kernel<false><<<C_CH, 512, SCAN_SMEM_BYTES>>>(out, out_size);
}